// round 8
// baseline (speedup 1.0000x reference)
#include <cuda_runtime.h>
#include <cuda_bf16.h>

// ODEFunc: per-point fused MLP forward + analytic gradient.
// f32x2 packed (2 points/lane) x NPAIR=2 pair-slots, with PAIRED weight loads:
// one LDS.128 fetches two replicated f32x2 weights and feeds FOUR FFMA2s
// (2 weights x 2 pair-slots). 128 B/warp/FFMA2 smem traffic (R5 level) at
// 0.25 LDS-instr/FFMA2 (half of R5). 64-thread blocks, natural regalloc ->
// warp-granular occupancy above R5's 8 warps/SM. Main net last, PW2T for the
// backward q-scan, in-place gq, (f^2-1) sign-cancellation.

using u64 = unsigned long long;

__device__ __forceinline__ u64 pk(float lo, float hi) {
    u64 r; asm("mov.b64 %0,{%1,%2};" : "=l"(r) : "f"(lo), "f"(hi)); return r;
}
__device__ __forceinline__ void upk(u64 v, float& lo, float& hi) {
    asm("mov.b64 {%0,%1},%2;" : "=f"(lo), "=f"(hi) : "l"(v));
}
__device__ __forceinline__ u64 fma2(u64 a, u64 b, u64 c) {
    u64 d; asm("fma.rn.f32x2 %0,%1,%2,%3;" : "=l"(d) : "l"(a), "l"(b), "l"(c)); return d;
}
__device__ __forceinline__ u64 mul2(u64 a, u64 b) {
    u64 d; asm("mul.rn.f32x2 %0,%1,%2;" : "=l"(d) : "l"(a), "l"(b)); return d;
}
__device__ __forceinline__ u64 add2(u64 a, u64 b) {
    u64 d; asm("add.rn.f32x2 %0,%1,%2;" : "=l"(d) : "l"(a), "l"(b)); return d;
}

#define MONE2 0xBF800000BF800000ULL  // (-1.0f, -1.0f)
#define HALF2 0x3F0000003F000000ULL  // ( 0.5f,  0.5f)

__device__ __forceinline__ float tanh_fast(float x) {
    float r; asm("tanh.approx.f32 %0,%1;" : "=f"(r) : "f"(x)); return r;
}
__device__ __forceinline__ float exp_fast(float x) {
    float r; asm("ex2.approx.f32 %0,%1;" : "=f"(r) : "f"(x * 1.4426950408889634f)); return r;
}
__device__ __forceinline__ float sigmoid_fast(float x) {
    return fmaf(0.5f, tanh_fast(0.5f * x), 0.5f);
}
__device__ __forceinline__ u64 tanh2(u64 v) {
    float a, b; upk(v, a, b);
    return pk(tanh_fast(a), tanh_fast(b));
}
__device__ __forceinline__ u64 elu2(u64 v) {
    float a, b; upk(v, a, b);
    a = a > 0.f ? a : (exp_fast(a) - 1.f);
    b = b > 0.f ? b : (exp_fast(b) - 1.f);
    return pk(a, b);
}

__device__ __forceinline__ ulonglong2 lds128(const u64* p) {
    return *reinterpret_cast<const ulonglong2*>(p);
}

#define NPAIR 2
#define NTHR 64

__global__ void __launch_bounds__(NTHR)
odefunc_kernel(const float* __restrict__ x,
               const float* __restrict__ mW0, const float* __restrict__ mb0,
               const float* __restrict__ mW1, const float* __restrict__ mb1,
               const float* __restrict__ mW2, const float* __restrict__ mb2,
               const float* __restrict__ pW1, const float* __restrict__ pb1,
               const float* __restrict__ pW2, const float* __restrict__ pb2,
               const float* __restrict__ pW3, const float* __restrict__ pb3,
               float* __restrict__ out, int npairs)
{
    // [0..342): segmented weights (replicated f32x2); [344..472): PW2 transposed
    __shared__ __align__(16) u64 wsm[472];
    {
        const float* srcs[12] = {mW0, mb0, mW1, mb1, mW2, mb2,
                                 pW1, pb1, pW2, pb2, pW3, pb3};
        const int offs[13] = {0, 16, 24, 88, 96, 128, 132, 164, 180, 308, 324, 340, 342};
        for (int idx = threadIdx.x; idx < 342; idx += blockDim.x) {
            int seg = 0;
            #pragma unroll
            for (int s2 = 0; s2 < 12; s2++)
                if (idx >= offs[s2 + 1]) seg = s2 + 1;
            float w = srcs[seg][idx - offs[seg]];
            wsm[idx] = pk(w, w);
        }
        for (int idx = threadIdx.x; idx < 128; idx += blockDim.x) {
            int v = idx >> 6, rem = idx & 63;
            int pp = rem >> 3, q = rem & 7;
            float w = pW2[v * 64 + q * 8 + pp];
            wsm[344 + idx] = pk(w, w);
        }
    }
    __syncthreads();

    const u64* W0   = wsm;         // 16 : [i*2+j]
    const u64* B0   = wsm + 16;    // 8
    const u64* W1   = wsm + 24;    // 64 : [i*8+j]
    const u64* B1   = wsm + 88;    // 8
    const u64* W2   = wsm + 96;    // 32 : [i*8+j]
    const u64* B2   = wsm + 128;   // 4
    const u64* PW1  = wsm + 132;   // 32 : [v*16+o*2+i]
    const u64* PB1  = wsm + 164;   // 16 : [v*8+o]
    const u64* PW2  = wsm + 180;   // 128: [v*64+q*8+p]
    const u64* PB2  = wsm + 308;   // 16 : [v*8+q]
    const u64* PW3  = wsm + 324;   // 16 : [v*8+p]
    const u64* PB3  = wsm + 340;   // 2  : [v]
    const u64* PW2T = wsm + 344;   // 128: [v*64+p*8+q]

    const long long base   = (long long)blockIdx.x * blockDim.x + threadIdx.x;
    const long long stride = (long long)gridDim.x * blockDim.x;

    long long pi[NPAIR];
    bool valid[NPAIR];
    u64 X0[NPAIR], X1[NPAIR];
    #pragma unroll
    for (int p = 0; p < NPAIR; p++) {
        pi[p] = base + (long long)p * stride;
        valid[p] = pi[p] < npairs;
        if (valid[p]) {
            float4 xx = reinterpret_cast<const float4*>(x)[pi[p]];
            X0[p] = pk(xx.x, xx.z);
            X1[p] = pk(xx.y, xx.w);
        } else {
            X0[p] = 0ULL; X1[p] = 0ULL;
        }
    }

    // ================= p nets (NV=2), forward + analytic backward =================
    u64 G0[NPAIR], G1[NPAIR];
    #pragma unroll
    for (int p = 0; p < NPAIR; p++) { G0[p] = 0ULL; G1[p] = 0ULL; }

    #pragma unroll
    for (int v = 0; v < 2; v++) {
        // f1 = tanh(x @ pW1^T + pb1), neuron-pairs share a bias LDS.128
        u64 f1[NPAIR][8];
        #pragma unroll
        for (int o = 0; o < 8; o += 2) {
            ulonglong2 wA = lds128(&PW1[v * 16 + o * 2]);       // neuron o
            ulonglong2 wB = lds128(&PW1[v * 16 + o * 2 + 2]);   // neuron o+1
            ulonglong2 bb2 = lds128(&PB1[v * 8 + o]);
            #pragma unroll
            for (int p = 0; p < NPAIR; p++) {
                f1[p][o]     = tanh2(fma2(X1[p], wA.y, fma2(X0[p], wA.x, bb2.x)));
                f1[p][o + 1] = tanh2(fma2(X1[p], wB.y, fma2(X0[p], wB.x, bb2.y)));
            }
        }

        // f2 = tanh(f1 @ pW2^T + pb2)
        u64 f2[NPAIR][8];
        #pragma unroll
        for (int q = 0; q < 8; q += 2) {
            ulonglong2 bb2 = lds128(&PB2[v * 8 + q]);
            u64 aA[NPAIR], aB[NPAIR], cA[NPAIR], cB[NPAIR];
            #pragma unroll
            for (int p = 0; p < NPAIR; p++) {
                aA[p] = bb2.x; cA[p] = 0ULL;   // neuron q
                aB[p] = bb2.y; cB[p] = 0ULL;   // neuron q+1
            }
            #pragma unroll
            for (int pp = 0; pp < 8; pp += 2) {
                ulonglong2 wA = lds128(&PW2[v * 64 + q * 8 + pp]);
                ulonglong2 wB = lds128(&PW2[v * 64 + (q + 1) * 8 + pp]);
                #pragma unroll
                for (int p = 0; p < NPAIR; p++) {
                    aA[p] = fma2(f1[p][pp],     wA.x, aA[p]);
                    cA[p] = fma2(f1[p][pp + 1], wA.y, cA[p]);
                    aB[p] = fma2(f1[p][pp],     wB.x, aB[p]);
                    cB[p] = fma2(f1[p][pp + 1], wB.y, cB[p]);
                }
            }
            #pragma unroll
            for (int p = 0; p < NPAIR; p++) {
                f2[p][q]     = tanh2(add2(aA[p], cA[p]));
                f2[p][q + 1] = tanh2(add2(aB[p], cB[p]));
            }
        }

        // z = f2 . pW3 + pb3 ; s = sigma(sigma(z)) ; ds = s(1-s)
        u64 DS[NPAIR];
        {
            u64 a0[NPAIR], a1[NPAIR];
            u64 b = PB3[v];
            #pragma unroll
            for (int p = 0; p < NPAIR; p++) { a0[p] = b; a1[p] = 0ULL; }
            #pragma unroll
            for (int pp = 0; pp < 8; pp += 2) {
                ulonglong2 w = lds128(&PW3[v * 8 + pp]);
                #pragma unroll
                for (int p = 0; p < NPAIR; p++) {
                    a0[p] = fma2(f2[p][pp],     w.x, a0[p]);
                    a1[p] = fma2(f2[p][pp + 1], w.y, a1[p]);
                }
            }
            #pragma unroll
            for (int p = 0; p < NPAIR; p++) {
                float za, zb; upk(add2(a0[p], a1[p]), za, zb);
                float sa = sigmoid_fast(sigmoid_fast(za));
                float sb = sigmoid_fast(sigmoid_fast(zb));
                DS[p] = pk(sa * (1.f - sa), sb * (1.f - sb));
            }
        }

        // gq'_q = ds * pW3_q * (f2_q^2 - 1)  (in place; sign cancels with gp)
        #pragma unroll
        for (int q = 0; q < 8; q += 2) {
            ulonglong2 w3 = lds128(&PW3[v * 8 + q]);
            #pragma unroll
            for (int p = 0; p < NPAIR; p++) {
                u64 u2a = fma2(f2[p][q],     f2[p][q],     MONE2);
                u64 u2b = fma2(f2[p][q + 1], f2[p][q + 1], MONE2);
                f2[p][q]     = mul2(mul2(DS[p], w3.x), u2a);
                f2[p][q + 1] = mul2(mul2(DS[p], w3.y), u2b);
            }
        }

        // gp_p = (sum_q gq'_q * W2[q,p]) * (f1_p^2 - 1); G += gp_p * pW1[p,:]
        #pragma unroll
        for (int pp = 0; pp < 8; pp++) {
            u64 a0[NPAIR], a1[NPAIR];
            #pragma unroll
            for (int p = 0; p < NPAIR; p++) { a0[p] = 0ULL; a1[p] = 0ULL; }
            #pragma unroll
            for (int q = 0; q < 8; q += 2) {
                ulonglong2 w = lds128(&PW2T[v * 64 + pp * 8 + q]);
                #pragma unroll
                for (int p = 0; p < NPAIR; p++) {
                    a0[p] = fma2(f2[p][q],     w.x, a0[p]);
                    a1[p] = fma2(f2[p][q + 1], w.y, a1[p]);
                }
            }
            ulonglong2 w1p = lds128(&PW1[v * 16 + pp * 2]);
            #pragma unroll
            for (int p = 0; p < NPAIR; p++) {
                u64 u1 = fma2(f1[p][pp], f1[p][pp], MONE2);
                u64 gpv = mul2(add2(a0[p], a1[p]), u1);
                G0[p] = fma2(gpv, w1p.x, G0[p]);
                G1[p] = fma2(gpv, w1p.y, G1[p]);
            }
        }
    }

    // ================= main net (last: only G carried across) =================
    u64 m2v[NPAIR], magA[NPAIR], magD[NPAIR];
    {
        u64 h0[NPAIR][8];
        #pragma unroll
        for (int i = 0; i < 8; i += 2) {
            ulonglong2 wA = lds128(&W0[i * 2]);
            ulonglong2 wB = lds128(&W0[i * 2 + 2]);
            ulonglong2 bb2 = lds128(&B0[i]);
            #pragma unroll
            for (int p = 0; p < NPAIR; p++) {
                h0[p][i]     = elu2(fma2(X1[p], wA.y, fma2(X0[p], wA.x, bb2.x)));
                h0[p][i + 1] = elu2(fma2(X1[p], wB.y, fma2(X0[p], wB.x, bb2.y)));
            }
        }

        u64 h1[NPAIR][8];
        #pragma unroll
        for (int i = 0; i < 8; i += 2) {
            ulonglong2 bb2 = lds128(&B1[i]);
            u64 aA[NPAIR], aB[NPAIR], cA[NPAIR], cB[NPAIR];
            #pragma unroll
            for (int p = 0; p < NPAIR; p++) {
                aA[p] = bb2.x; cA[p] = 0ULL;
                aB[p] = bb2.y; cB[p] = 0ULL;
            }
            #pragma unroll
            for (int j = 0; j < 8; j += 2) {
                ulonglong2 wA = lds128(&W1[i * 8 + j]);
                ulonglong2 wB = lds128(&W1[(i + 1) * 8 + j]);
                #pragma unroll
                for (int p = 0; p < NPAIR; p++) {
                    aA[p] = fma2(h0[p][j],     wA.x, aA[p]);
                    cA[p] = fma2(h0[p][j + 1], wA.y, cA[p]);
                    aB[p] = fma2(h0[p][j],     wB.x, aB[p]);
                    cB[p] = fma2(h0[p][j + 1], wB.y, cB[p]);
                }
            }
            #pragma unroll
            for (int p = 0; p < NPAIR; p++) {
                h1[p][i]     = elu2(add2(aA[p], cA[p]));
                h1[p][i + 1] = elu2(add2(aB[p], cB[p]));
            }
        }

        u64 bb[NPAIR][4];
        #pragma unroll
        for (int i = 0; i < 4; i += 2) {
            ulonglong2 bb2 = lds128(&B2[i]);
            u64 aA[NPAIR], aB[NPAIR], cA[NPAIR], cB[NPAIR];
            #pragma unroll
            for (int p = 0; p < NPAIR; p++) {
                aA[p] = bb2.x; cA[p] = 0ULL;
                aB[p] = bb2.y; cB[p] = 0ULL;
            }
            #pragma unroll
            for (int j = 0; j < 8; j += 2) {
                ulonglong2 wA = lds128(&W2[i * 8 + j]);
                ulonglong2 wB = lds128(&W2[(i + 1) * 8 + j]);
                #pragma unroll
                for (int p = 0; p < NPAIR; p++) {
                    aA[p] = fma2(h1[p][j],     wA.x, aA[p]);
                    cA[p] = fma2(h1[p][j + 1], wA.y, cA[p]);
                    aB[p] = fma2(h1[p][j],     wB.x, aB[p]);
                    cB[p] = fma2(h1[p][j + 1], wB.y, cB[p]);
                }
            }
            #pragma unroll
            for (int p = 0; p < NPAIR; p++) {
                bb[p][i]     = add2(aA[p], cA[p]);
                bb[p][i + 1] = add2(aB[p], cB[p]);
            }
        }
        #pragma unroll
        for (int p = 0; p < NPAIR; p++) {
            m2v[p]  = fma2(bb[p][0], bb[p][1], mul2(bb[p][2], bb[p][3]));
            magA[p] = fma2(bb[p][0], bb[p][0], mul2(bb[p][2], bb[p][2]));
            magD[p] = fma2(bb[p][1], bb[p][1], mul2(bb[p][3], bb[p][3]));
        }
    }

    // out0 = 0.5*(magA*G0 + m2*G1); out1 = 0.5*(m2*G0 + magD*G1)
    #pragma unroll
    for (int p = 0; p < NPAIR; p++) {
        if (!valid[p]) continue;
        u64 o0 = mul2(HALF2, fma2(magA[p], G0[p], mul2(m2v[p], G1[p])));
        u64 o1 = mul2(HALF2, fma2(m2v[p], G0[p], mul2(magD[p], G1[p])));
        float a0, b0c, a1, b1c;
        upk(o0, a0, b0c);
        upk(o1, a1, b1c);
        reinterpret_cast<float4*>(out)[pi[p]] = make_float4(a0, a1, b0c, b1c);
    }
}

extern "C" void kernel_launch(void* const* d_in, const int* in_sizes, int n_in,
                              void* d_out, int out_size)
{
    const float* x   = (const float*)d_in[1];
    const float* mW0 = (const float*)d_in[2];
    const float* mb0 = (const float*)d_in[3];
    const float* mW1 = (const float*)d_in[4];
    const float* mb1 = (const float*)d_in[5];
    const float* mW2 = (const float*)d_in[6];
    const float* mb2 = (const float*)d_in[7];
    const float* pW1 = (const float*)d_in[8];
    const float* pb1 = (const float*)d_in[9];
    const float* pW2 = (const float*)d_in[10];
    const float* pb2 = (const float*)d_in[11];
    const float* pW3 = (const float*)d_in[12];
    const float* pb3 = (const float*)d_in[13];

    int B = in_sizes[1] / 2;       // x is (B, 2)
    int npairs = B / 2;
    int threads = NTHR;
    long long tot_threads = (npairs + NPAIR - 1) / NPAIR;
    int blocks = (int)((tot_threads + threads - 1) / threads);

    odefunc_kernel<<<blocks, threads>>>(x, mW0, mb0, mW1, mb1, mW2, mb2,
                                        pW1, pb1, pW2, pb2, pW3, pb3,
                                        (float*)d_out, npairs);
}

// round 9
// speedup vs baseline: 1.1419x; 1.1419x over previous
#include <cuda_runtime.h>
#include <cuda_bf16.h>

// ODEFunc: per-point fused MLP forward + analytic gradient.
// f32x2 packed (2 points/lane) x NPAIR=2 pair-slots. PAIRED weight loads:
// one LDS.128 = two replicated f32x2 weights = four FFMA2s fed.
// Lean R5-style loop shape (2 accumulator chains per neuron, not R8's 4-acc
// bundles) + launch_bounds(128,3) -> 170-reg cap -> 3 warps/SMSP (12/SM),
// one tier above the 255-reg/8-warp R5 baseline. Main net last, PW2T
// transposed backward scan, in-place gq, (f^2-1) sign cancellation.

using u64 = unsigned long long;

__device__ __forceinline__ u64 pk(float lo, float hi) {
    u64 r; asm("mov.b64 %0,{%1,%2};" : "=l"(r) : "f"(lo), "f"(hi)); return r;
}
__device__ __forceinline__ void upk(u64 v, float& lo, float& hi) {
    asm("mov.b64 {%0,%1},%2;" : "=f"(lo), "=f"(hi) : "l"(v));
}
__device__ __forceinline__ u64 fma2(u64 a, u64 b, u64 c) {
    u64 d; asm("fma.rn.f32x2 %0,%1,%2,%3;" : "=l"(d) : "l"(a), "l"(b), "l"(c)); return d;
}
__device__ __forceinline__ u64 mul2(u64 a, u64 b) {
    u64 d; asm("mul.rn.f32x2 %0,%1,%2;" : "=l"(d) : "l"(a), "l"(b)); return d;
}
__device__ __forceinline__ u64 add2(u64 a, u64 b) {
    u64 d; asm("add.rn.f32x2 %0,%1,%2;" : "=l"(d) : "l"(a), "l"(b)); return d;
}

#define MONE2 0xBF800000BF800000ULL  // (-1.0f, -1.0f)
#define HALF2 0x3F0000003F000000ULL  // ( 0.5f,  0.5f)

__device__ __forceinline__ float tanh_fast(float x) {
    float r; asm("tanh.approx.f32 %0,%1;" : "=f"(r) : "f"(x)); return r;
}
__device__ __forceinline__ float exp_fast(float x) {
    float r; asm("ex2.approx.f32 %0,%1;" : "=f"(r) : "f"(x * 1.4426950408889634f)); return r;
}
__device__ __forceinline__ float sigmoid_fast(float x) {
    return fmaf(0.5f, tanh_fast(0.5f * x), 0.5f);
}
__device__ __forceinline__ u64 tanh2(u64 v) {
    float a, b; upk(v, a, b);
    return pk(tanh_fast(a), tanh_fast(b));
}
__device__ __forceinline__ u64 elu2(u64 v) {
    float a, b; upk(v, a, b);
    a = a > 0.f ? a : (exp_fast(a) - 1.f);
    b = b > 0.f ? b : (exp_fast(b) - 1.f);
    return pk(a, b);
}

__device__ __forceinline__ ulonglong2 lds128(const u64* p) {
    return *reinterpret_cast<const ulonglong2*>(p);
}

#define NPAIR 2
#define NTHR 128

__global__ void __launch_bounds__(NTHR, 3)
odefunc_kernel(const float* __restrict__ x,
               const float* __restrict__ mW0, const float* __restrict__ mb0,
               const float* __restrict__ mW1, const float* __restrict__ mb1,
               const float* __restrict__ mW2, const float* __restrict__ mb2,
               const float* __restrict__ pW1, const float* __restrict__ pb1,
               const float* __restrict__ pW2, const float* __restrict__ pb2,
               const float* __restrict__ pW3, const float* __restrict__ pb3,
               float* __restrict__ out, int npairs)
{
    // [0..342): segmented weights (replicated f32x2); [344..472): PW2 transposed
    __shared__ __align__(16) u64 wsm[472];
    {
        const float* srcs[12] = {mW0, mb0, mW1, mb1, mW2, mb2,
                                 pW1, pb1, pW2, pb2, pW3, pb3};
        const int offs[13] = {0, 16, 24, 88, 96, 128, 132, 164, 180, 308, 324, 340, 342};
        for (int idx = threadIdx.x; idx < 342; idx += blockDim.x) {
            int seg = 0;
            #pragma unroll
            for (int s2 = 0; s2 < 12; s2++)
                if (idx >= offs[s2 + 1]) seg = s2 + 1;
            float w = srcs[seg][idx - offs[seg]];
            wsm[idx] = pk(w, w);
        }
        for (int idx = threadIdx.x; idx < 128; idx += blockDim.x) {
            int v = idx >> 6, rem = idx & 63;
            int pp = rem >> 3, q = rem & 7;
            float w = pW2[v * 64 + q * 8 + pp];
            wsm[344 + idx] = pk(w, w);
        }
    }
    __syncthreads();

    const u64* W0   = wsm;         // 16 : [i*2+j]
    const u64* B0   = wsm + 16;    // 8
    const u64* W1   = wsm + 24;    // 64 : [i*8+j]
    const u64* B1   = wsm + 88;    // 8
    const u64* W2   = wsm + 96;    // 32 : [i*8+j]
    const u64* B2   = wsm + 128;   // 4
    const u64* PW1  = wsm + 132;   // 32 : [v*16+o*2+i]
    const u64* PB1  = wsm + 164;   // 16 : [v*8+o]
    const u64* PW2  = wsm + 180;   // 128: [v*64+q*8+p]
    const u64* PB2  = wsm + 308;   // 16 : [v*8+q]
    const u64* PW3  = wsm + 324;   // 16 : [v*8+p]
    const u64* PB3  = wsm + 340;   // 2  : [v]
    const u64* PW2T = wsm + 344;   // 128: [v*64+p*8+q]

    const long long base   = (long long)blockIdx.x * blockDim.x + threadIdx.x;
    const long long stride = (long long)gridDim.x * blockDim.x;

    long long pi[NPAIR];
    bool valid[NPAIR];
    u64 X0[NPAIR], X1[NPAIR];
    #pragma unroll
    for (int p = 0; p < NPAIR; p++) {
        pi[p] = base + (long long)p * stride;
        valid[p] = pi[p] < npairs;
        if (valid[p]) {
            float4 xx = reinterpret_cast<const float4*>(x)[pi[p]];
            X0[p] = pk(xx.x, xx.z);
            X1[p] = pk(xx.y, xx.w);
        } else {
            X0[p] = 0ULL; X1[p] = 0ULL;
        }
    }

    // ================= p nets (NV=2), forward + analytic backward =================
    u64 G0[NPAIR], G1[NPAIR];
    #pragma unroll
    for (int p = 0; p < NPAIR; p++) { G0[p] = 0ULL; G1[p] = 0ULL; }

    #pragma unroll
    for (int v = 0; v < 2; v++) {
        // f1 = tanh(x @ pW1^T + pb1): pW1 row (2 coords) = exactly one LDS.128
        u64 f1[NPAIR][8];
        #pragma unroll
        for (int o = 0; o < 8; o++) {
            ulonglong2 w = lds128(&PW1[v * 16 + o * 2]);
            u64 b = PB1[v * 8 + o];
            #pragma unroll
            for (int p = 0; p < NPAIR; p++)
                f1[p][o] = tanh2(fma2(X1[p], w.y, fma2(X0[p], w.x, b)));
        }

        // f2 = tanh(f1 @ pW2^T + pb2): one q at a time, LDS.128 along pp
        u64 f2[NPAIR][8];
        #pragma unroll
        for (int q = 0; q < 8; q++) {
            u64 a0[NPAIR], a1[NPAIR];
            u64 b = PB2[v * 8 + q];
            #pragma unroll
            for (int p = 0; p < NPAIR; p++) { a0[p] = b; a1[p] = 0ULL; }
            #pragma unroll
            for (int pp = 0; pp < 8; pp += 2) {
                ulonglong2 w = lds128(&PW2[v * 64 + q * 8 + pp]);
                #pragma unroll
                for (int p = 0; p < NPAIR; p++) {
                    a0[p] = fma2(f1[p][pp],     w.x, a0[p]);
                    a1[p] = fma2(f1[p][pp + 1], w.y, a1[p]);
                }
            }
            #pragma unroll
            for (int p = 0; p < NPAIR; p++) f2[p][q] = tanh2(add2(a0[p], a1[p]));
        }

        // z = f2 . pW3 + pb3 ; s = sigma(sigma(z)) ; ds = s(1-s)
        u64 DS[NPAIR];
        {
            u64 a0[NPAIR], a1[NPAIR];
            u64 b = PB3[v];
            #pragma unroll
            for (int p = 0; p < NPAIR; p++) { a0[p] = b; a1[p] = 0ULL; }
            #pragma unroll
            for (int pp = 0; pp < 8; pp += 2) {
                ulonglong2 w = lds128(&PW3[v * 8 + pp]);
                #pragma unroll
                for (int p = 0; p < NPAIR; p++) {
                    a0[p] = fma2(f2[p][pp],     w.x, a0[p]);
                    a1[p] = fma2(f2[p][pp + 1], w.y, a1[p]);
                }
            }
            #pragma unroll
            for (int p = 0; p < NPAIR; p++) {
                float za, zb; upk(add2(a0[p], a1[p]), za, zb);
                float sa = sigmoid_fast(sigmoid_fast(za));
                float sb = sigmoid_fast(sigmoid_fast(zb));
                DS[p] = pk(sa * (1.f - sa), sb * (1.f - sb));
            }
        }

        // gq'_q = ds * pW3_q * (f2_q^2 - 1)  (in place; sign cancels with gp)
        #pragma unroll
        for (int q = 0; q < 8; q += 2) {
            ulonglong2 w3 = lds128(&PW3[v * 8 + q]);
            #pragma unroll
            for (int p = 0; p < NPAIR; p++) {
                u64 u2a = fma2(f2[p][q],     f2[p][q],     MONE2);
                u64 u2b = fma2(f2[p][q + 1], f2[p][q + 1], MONE2);
                f2[p][q]     = mul2(mul2(DS[p], w3.x), u2a);
                f2[p][q + 1] = mul2(mul2(DS[p], w3.y), u2b);
            }
        }

        // gp_p = (sum_q gq'_q * W2[q,p]) * (f1_p^2 - 1); G += gp_p * pW1[p,:]
        #pragma unroll
        for (int pp = 0; pp < 8; pp++) {
            u64 a0[NPAIR], a1[NPAIR];
            #pragma unroll
            for (int p = 0; p < NPAIR; p++) { a0[p] = 0ULL; a1[p] = 0ULL; }
            #pragma unroll
            for (int q = 0; q < 8; q += 2) {
                ulonglong2 w = lds128(&PW2T[v * 64 + pp * 8 + q]);
                #pragma unroll
                for (int p = 0; p < NPAIR; p++) {
                    a0[p] = fma2(f2[p][q],     w.x, a0[p]);
                    a1[p] = fma2(f2[p][q + 1], w.y, a1[p]);
                }
            }
            ulonglong2 w1p = lds128(&PW1[v * 16 + pp * 2]);
            #pragma unroll
            for (int p = 0; p < NPAIR; p++) {
                u64 u1 = fma2(f1[p][pp], f1[p][pp], MONE2);
                u64 gpv = mul2(add2(a0[p], a1[p]), u1);
                G0[p] = fma2(gpv, w1p.x, G0[p]);
                G1[p] = fma2(gpv, w1p.y, G1[p]);
            }
        }
    }

    // ================= main net (last: only G carried across) =================
    u64 m2v[NPAIR], magA[NPAIR], magD[NPAIR];
    {
        u64 h0[NPAIR][8];
        #pragma unroll
        for (int i = 0; i < 8; i++) {
            ulonglong2 w = lds128(&W0[i * 2]);
            u64 b = B0[i];
            #pragma unroll
            for (int p = 0; p < NPAIR; p++)
                h0[p][i] = elu2(fma2(X1[p], w.y, fma2(X0[p], w.x, b)));
        }

        u64 h1[NPAIR][8];
        #pragma unroll
        for (int i = 0; i < 8; i++) {
            u64 a0[NPAIR], a1[NPAIR];
            u64 b = B1[i];
            #pragma unroll
            for (int p = 0; p < NPAIR; p++) { a0[p] = b; a1[p] = 0ULL; }
            #pragma unroll
            for (int j = 0; j < 8; j += 2) {
                ulonglong2 w = lds128(&W1[i * 8 + j]);
                #pragma unroll
                for (int p = 0; p < NPAIR; p++) {
                    a0[p] = fma2(h0[p][j],     w.x, a0[p]);
                    a1[p] = fma2(h0[p][j + 1], w.y, a1[p]);
                }
            }
            #pragma unroll
            for (int p = 0; p < NPAIR; p++) h1[p][i] = elu2(add2(a0[p], a1[p]));
        }

        u64 bb[NPAIR][4];
        #pragma unroll
        for (int i = 0; i < 4; i++) {
            u64 a0[NPAIR], a1[NPAIR];
            u64 b = B2[i];
            #pragma unroll
            for (int p = 0; p < NPAIR; p++) { a0[p] = b; a1[p] = 0ULL; }
            #pragma unroll
            for (int j = 0; j < 8; j += 2) {
                ulonglong2 w = lds128(&W2[i * 8 + j]);
                #pragma unroll
                for (int p = 0; p < NPAIR; p++) {
                    a0[p] = fma2(h1[p][j],     w.x, a0[p]);
                    a1[p] = fma2(h1[p][j + 1], w.y, a1[p]);
                }
            }
            #pragma unroll
            for (int p = 0; p < NPAIR; p++) bb[p][i] = add2(a0[p], a1[p]);
        }
        #pragma unroll
        for (int p = 0; p < NPAIR; p++) {
            m2v[p]  = fma2(bb[p][0], bb[p][1], mul2(bb[p][2], bb[p][3]));
            magA[p] = fma2(bb[p][0], bb[p][0], mul2(bb[p][2], bb[p][2]));
            magD[p] = fma2(bb[p][1], bb[p][1], mul2(bb[p][3], bb[p][3]));
        }
    }

    // out0 = 0.5*(magA*G0 + m2*G1); out1 = 0.5*(m2*G0 + magD*G1)
    #pragma unroll
    for (int p = 0; p < NPAIR; p++) {
        if (!valid[p]) continue;
        u64 o0 = mul2(HALF2, fma2(magA[p], G0[p], mul2(m2v[p], G1[p])));
        u64 o1 = mul2(HALF2, fma2(m2v[p], G0[p], mul2(magD[p], G1[p])));
        float a0, b0c, a1, b1c;
        upk(o0, a0, b0c);
        upk(o1, a1, b1c);
        reinterpret_cast<float4*>(out)[pi[p]] = make_float4(a0, a1, b0c, b1c);
    }
}

extern "C" void kernel_launch(void* const* d_in, const int* in_sizes, int n_in,
                              void* d_out, int out_size)
{
    const float* x   = (const float*)d_in[1];
    const float* mW0 = (const float*)d_in[2];
    const float* mb0 = (const float*)d_in[3];
    const float* mW1 = (const float*)d_in[4];
    const float* mb1 = (const float*)d_in[5];
    const float* mW2 = (const float*)d_in[6];
    const float* mb2 = (const float*)d_in[7];
    const float* pW1 = (const float*)d_in[8];
    const float* pb1 = (const float*)d_in[9];
    const float* pW2 = (const float*)d_in[10];
    const float* pb2 = (const float*)d_in[11];
    const float* pW3 = (const float*)d_in[12];
    const float* pb3 = (const float*)d_in[13];

    int B = in_sizes[1] / 2;       // x is (B, 2)
    int npairs = B / 2;
    int threads = NTHR;
    long long tot_threads = (npairs + NPAIR - 1) / NPAIR;
    int blocks = (int)((tot_threads + threads - 1) / threads);

    odefunc_kernel<<<blocks, threads>>>(x, mW0, mb0, mW1, mb1, mW2, mb2,
                                        pW1, pb1, pW2, pb2, pW3, pb3,
                                        (float*)d_out, npairs);
}

// round 10
// speedup vs baseline: 1.3699x; 1.1997x over previous
#include <cuda_runtime.h>
#include <cuda_bf16.h>

// ODEFunc: per-point fused MLP forward + analytic gradient.
// f32x2 packed (2 points/lane) x NPAIR=2 pair-slots. One LDS.128 = two
// replicated f32x2 weights = four FFMA2s fed. launch_bounds(128,3) ->
// 168 regs, 12 warps/SM, no spill (R9-proven). New in R10:
//  - DS (sigmoid-chain) factored out of gq: backward DAG no longer waits on
//    the ~50-cyc f3/sigmoid dependency chain; G = fma2(DS, PG, G) at v end.
//  - branch-free ELU: max(x, exp(min(x,0))-1) -- no predicates.

using u64 = unsigned long long;

__device__ __forceinline__ u64 pk(float lo, float hi) {
    u64 r; asm("mov.b64 %0,{%1,%2};" : "=l"(r) : "f"(lo), "f"(hi)); return r;
}
__device__ __forceinline__ void upk(u64 v, float& lo, float& hi) {
    asm("mov.b64 {%0,%1},%2;" : "=f"(lo), "=f"(hi) : "l"(v));
}
__device__ __forceinline__ u64 fma2(u64 a, u64 b, u64 c) {
    u64 d; asm("fma.rn.f32x2 %0,%1,%2,%3;" : "=l"(d) : "l"(a), "l"(b), "l"(c)); return d;
}
__device__ __forceinline__ u64 mul2(u64 a, u64 b) {
    u64 d; asm("mul.rn.f32x2 %0,%1,%2;" : "=l"(d) : "l"(a), "l"(b)); return d;
}
__device__ __forceinline__ u64 add2(u64 a, u64 b) {
    u64 d; asm("add.rn.f32x2 %0,%1,%2;" : "=l"(d) : "l"(a), "l"(b)); return d;
}

#define MONE2 0xBF800000BF800000ULL  // (-1.0f, -1.0f)
#define HALF2 0x3F0000003F000000ULL  // ( 0.5f,  0.5f)

__device__ __forceinline__ float tanh_fast(float x) {
    float r; asm("tanh.approx.f32 %0,%1;" : "=f"(r) : "f"(x)); return r;
}
__device__ __forceinline__ float exp_fast(float x) {
    float r; asm("ex2.approx.f32 %0,%1;" : "=f"(r) : "f"(x * 1.4426950408889634f)); return r;
}
__device__ __forceinline__ float sigmoid_fast(float x) {
    return fmaf(0.5f, tanh_fast(0.5f * x), 0.5f);
}
__device__ __forceinline__ u64 tanh2(u64 v) {
    float a, b; upk(v, a, b);
    return pk(tanh_fast(a), tanh_fast(b));
}
// branch-free ELU: max(x, exp(min(x,0)) - 1); exact for x>0 since ex2(0)=1
__device__ __forceinline__ u64 elu2(u64 v) {
    float a, b; upk(v, a, b);
    a = fmaxf(a, exp_fast(fminf(a, 0.f)) - 1.f);
    b = fmaxf(b, exp_fast(fminf(b, 0.f)) - 1.f);
    return pk(a, b);
}

__device__ __forceinline__ ulonglong2 lds128(const u64* p) {
    return *reinterpret_cast<const ulonglong2*>(p);
}

#define NPAIR 2
#define NTHR 128

__global__ void __launch_bounds__(NTHR, 3)
odefunc_kernel(const float* __restrict__ x,
               const float* __restrict__ mW0, const float* __restrict__ mb0,
               const float* __restrict__ mW1, const float* __restrict__ mb1,
               const float* __restrict__ mW2, const float* __restrict__ mb2,
               const float* __restrict__ pW1, const float* __restrict__ pb1,
               const float* __restrict__ pW2, const float* __restrict__ pb2,
               const float* __restrict__ pW3, const float* __restrict__ pb3,
               float* __restrict__ out, int npairs)
{
    // [0..342): segmented weights (replicated f32x2); [344..472): PW2 transposed
    __shared__ __align__(16) u64 wsm[472];
    {
        const float* srcs[12] = {mW0, mb0, mW1, mb1, mW2, mb2,
                                 pW1, pb1, pW2, pb2, pW3, pb3};
        const int offs[13] = {0, 16, 24, 88, 96, 128, 132, 164, 180, 308, 324, 340, 342};
        for (int idx = threadIdx.x; idx < 342; idx += blockDim.x) {
            int seg = 0;
            #pragma unroll
            for (int s2 = 0; s2 < 12; s2++)
                if (idx >= offs[s2 + 1]) seg = s2 + 1;
            float w = srcs[seg][idx - offs[seg]];
            wsm[idx] = pk(w, w);
        }
        for (int idx = threadIdx.x; idx < 128; idx += blockDim.x) {
            int v = idx >> 6, rem = idx & 63;
            int pp = rem >> 3, q = rem & 7;
            float w = pW2[v * 64 + q * 8 + pp];
            wsm[344 + idx] = pk(w, w);
        }
    }
    __syncthreads();

    const u64* W0   = wsm;         // 16 : [i*2+j]
    const u64* B0   = wsm + 16;    // 8
    const u64* W1   = wsm + 24;    // 64 : [i*8+j]
    const u64* B1   = wsm + 88;    // 8
    const u64* W2   = wsm + 96;    // 32 : [i*8+j]
    const u64* B2   = wsm + 128;   // 4
    const u64* PW1  = wsm + 132;   // 32 : [v*16+o*2+i]
    const u64* PB1  = wsm + 164;   // 16 : [v*8+o]
    const u64* PW2  = wsm + 180;   // 128: [v*64+q*8+p]
    const u64* PB2  = wsm + 308;   // 16 : [v*8+q]
    const u64* PW3  = wsm + 324;   // 16 : [v*8+p]
    const u64* PB3  = wsm + 340;   // 2  : [v]
    const u64* PW2T = wsm + 344;   // 128: [v*64+p*8+q]

    const long long base   = (long long)blockIdx.x * blockDim.x + threadIdx.x;
    const long long stride = (long long)gridDim.x * blockDim.x;

    long long pi[NPAIR];
    bool valid[NPAIR];
    u64 X0[NPAIR], X1[NPAIR];
    #pragma unroll
    for (int p = 0; p < NPAIR; p++) {
        pi[p] = base + (long long)p * stride;
        valid[p] = pi[p] < npairs;
        if (valid[p]) {
            float4 xx = reinterpret_cast<const float4*>(x)[pi[p]];
            X0[p] = pk(xx.x, xx.z);
            X1[p] = pk(xx.y, xx.w);
        } else {
            X0[p] = 0ULL; X1[p] = 0ULL;
        }
    }

    // ================= p nets (NV=2), forward + analytic backward =================
    u64 G0[NPAIR], G1[NPAIR];
    #pragma unroll
    for (int p = 0; p < NPAIR; p++) { G0[p] = 0ULL; G1[p] = 0ULL; }

    #pragma unroll
    for (int v = 0; v < 2; v++) {
        // f1 = tanh(x @ pW1^T + pb1): one LDS.128 per neuron row
        u64 f1[NPAIR][8];
        #pragma unroll
        for (int o = 0; o < 8; o++) {
            ulonglong2 w = lds128(&PW1[v * 16 + o * 2]);
            u64 b = PB1[v * 8 + o];
            #pragma unroll
            for (int p = 0; p < NPAIR; p++)
                f1[p][o] = tanh2(fma2(X1[p], w.y, fma2(X0[p], w.x, b)));
        }

        // f2 = tanh(f1 @ pW2^T + pb2)
        u64 f2[NPAIR][8];
        #pragma unroll
        for (int q = 0; q < 8; q++) {
            u64 a0[NPAIR], a1[NPAIR];
            u64 b = PB2[v * 8 + q];
            #pragma unroll
            for (int p = 0; p < NPAIR; p++) { a0[p] = b; a1[p] = 0ULL; }
            #pragma unroll
            for (int pp = 0; pp < 8; pp += 2) {
                ulonglong2 w = lds128(&PW2[v * 64 + q * 8 + pp]);
                #pragma unroll
                for (int p = 0; p < NPAIR; p++) {
                    a0[p] = fma2(f1[p][pp],     w.x, a0[p]);
                    a1[p] = fma2(f1[p][pp + 1], w.y, a1[p]);
                }
            }
            #pragma unroll
            for (int p = 0; p < NPAIR; p++) f2[p][q] = tanh2(add2(a0[p], a1[p]));
        }

        // z = f2 . pW3 + pb3 ; s = sigma(sigma(z)) ; DS = s(1-s)
        // (DS chain is now INDEPENDENT of the backward below -- overlaps fully)
        u64 DS[NPAIR];
        {
            u64 a0[NPAIR], a1[NPAIR];
            u64 b = PB3[v];
            #pragma unroll
            for (int p = 0; p < NPAIR; p++) { a0[p] = b; a1[p] = 0ULL; }
            #pragma unroll
            for (int pp = 0; pp < 8; pp += 2) {
                ulonglong2 w = lds128(&PW3[v * 8 + pp]);
                #pragma unroll
                for (int p = 0; p < NPAIR; p++) {
                    a0[p] = fma2(f2[p][pp],     w.x, a0[p]);
                    a1[p] = fma2(f2[p][pp + 1], w.y, a1[p]);
                }
            }
            #pragma unroll
            for (int p = 0; p < NPAIR; p++) {
                float za, zb; upk(add2(a0[p], a1[p]), za, zb);
                float sa = sigmoid_fast(sigmoid_fast(za));
                float sb = sigmoid_fast(sigmoid_fast(zb));
                DS[p] = pk(sa * (1.f - sa), sb * (1.f - sb));
            }
        }

        // gq'_q = w3_q * (f2_q^2 - 1)   (DS factored out; sign cancels with gp)
        #pragma unroll
        for (int q = 0; q < 8; q += 2) {
            ulonglong2 w3 = lds128(&PW3[v * 8 + q]);
            #pragma unroll
            for (int p = 0; p < NPAIR; p++) {
                u64 u2a = fma2(f2[p][q],     f2[p][q],     MONE2);
                u64 u2b = fma2(f2[p][q + 1], f2[p][q + 1], MONE2);
                f2[p][q]     = mul2(w3.x, u2a);
                f2[p][q + 1] = mul2(w3.y, u2b);
            }
        }

        // PG_p = sum_pp [(sum_q gq'_q W2[q,pp]) * (f1_pp^2-1)] * pW1[pp,:]
        u64 PG0[NPAIR], PG1[NPAIR];
        #pragma unroll
        for (int p = 0; p < NPAIR; p++) { PG0[p] = 0ULL; PG1[p] = 0ULL; }
        #pragma unroll
        for (int pp = 0; pp < 8; pp++) {
            u64 a0[NPAIR], a1[NPAIR];
            #pragma unroll
            for (int p = 0; p < NPAIR; p++) { a0[p] = 0ULL; a1[p] = 0ULL; }
            #pragma unroll
            for (int q = 0; q < 8; q += 2) {
                ulonglong2 w = lds128(&PW2T[v * 64 + pp * 8 + q]);
                #pragma unroll
                for (int p = 0; p < NPAIR; p++) {
                    a0[p] = fma2(f2[p][q],     w.x, a0[p]);
                    a1[p] = fma2(f2[p][q + 1], w.y, a1[p]);
                }
            }
            ulonglong2 w1p = lds128(&PW1[v * 16 + pp * 2]);
            #pragma unroll
            for (int p = 0; p < NPAIR; p++) {
                u64 u1 = fma2(f1[p][pp], f1[p][pp], MONE2);
                u64 gpv = mul2(add2(a0[p], a1[p]), u1);
                PG0[p] = fma2(gpv, w1p.x, PG0[p]);
                PG1[p] = fma2(gpv, w1p.y, PG1[p]);
            }
        }
        // fold DS in once per v
        #pragma unroll
        for (int p = 0; p < NPAIR; p++) {
            G0[p] = fma2(DS[p], PG0[p], G0[p]);
            G1[p] = fma2(DS[p], PG1[p], G1[p]);
        }
    }

    // ================= main net (last: only G carried across) =================
    u64 m2v[NPAIR], magA[NPAIR], magD[NPAIR];
    {
        u64 h0[NPAIR][8];
        #pragma unroll
        for (int i = 0; i < 8; i++) {
            ulonglong2 w = lds128(&W0[i * 2]);
            u64 b = B0[i];
            #pragma unroll
            for (int p = 0; p < NPAIR; p++)
                h0[p][i] = elu2(fma2(X1[p], w.y, fma2(X0[p], w.x, b)));
        }

        u64 h1[NPAIR][8];
        #pragma unroll
        for (int i = 0; i < 8; i++) {
            u64 a0[NPAIR], a1[NPAIR];
            u64 b = B1[i];
            #pragma unroll
            for (int p = 0; p < NPAIR; p++) { a0[p] = b; a1[p] = 0ULL; }
            #pragma unroll
            for (int j = 0; j < 8; j += 2) {
                ulonglong2 w = lds128(&W1[i * 8 + j]);
                #pragma unroll
                for (int p = 0; p < NPAIR; p++) {
                    a0[p] = fma2(h0[p][j],     w.x, a0[p]);
                    a1[p] = fma2(h0[p][j + 1], w.y, a1[p]);
                }
            }
            #pragma unroll
            for (int p = 0; p < NPAIR; p++) h1[p][i] = elu2(add2(a0[p], a1[p]));
        }

        u64 bb[NPAIR][4];
        #pragma unroll
        for (int i = 0; i < 4; i++) {
            u64 a0[NPAIR], a1[NPAIR];
            u64 b = B2[i];
            #pragma unroll
            for (int p = 0; p < NPAIR; p++) { a0[p] = b; a1[p] = 0ULL; }
            #pragma unroll
            for (int j = 0; j < 8; j += 2) {
                ulonglong2 w = lds128(&W2[i * 8 + j]);
                #pragma unroll
                for (int p = 0; p < NPAIR; p++) {
                    a0[p] = fma2(h1[p][j],     w.x, a0[p]);
                    a1[p] = fma2(h1[p][j + 1], w.y, a1[p]);
                }
            }
            #pragma unroll
            for (int p = 0; p < NPAIR; p++) bb[p][i] = add2(a0[p], a1[p]);
        }
        #pragma unroll
        for (int p = 0; p < NPAIR; p++) {
            m2v[p]  = fma2(bb[p][0], bb[p][1], mul2(bb[p][2], bb[p][3]));
            magA[p] = fma2(bb[p][0], bb[p][0], mul2(bb[p][2], bb[p][2]));
            magD[p] = fma2(bb[p][1], bb[p][1], mul2(bb[p][3], bb[p][3]));
        }
    }

    // out0 = 0.5*(magA*G0 + m2*G1); out1 = 0.5*(m2*G0 + magD*G1)
    #pragma unroll
    for (int p = 0; p < NPAIR; p++) {
        if (!valid[p]) continue;
        u64 o0 = mul2(HALF2, fma2(magA[p], G0[p], mul2(m2v[p], G1[p])));
        u64 o1 = mul2(HALF2, fma2(m2v[p], G0[p], mul2(magD[p], G1[p])));
        float a0, b0c, a1, b1c;
        upk(o0, a0, b0c);
        upk(o1, a1, b1c);
        reinterpret_cast<float4*>(out)[pi[p]] = make_float4(a0, a1, b0c, b1c);
    }
}

extern "C" void kernel_launch(void* const* d_in, const int* in_sizes, int n_in,
                              void* d_out, int out_size)
{
    const float* x   = (const float*)d_in[1];
    const float* mW0 = (const float*)d_in[2];
    const float* mb0 = (const float*)d_in[3];
    const float* mW1 = (const float*)d_in[4];
    const float* mb1 = (const float*)d_in[5];
    const float* mW2 = (const float*)d_in[6];
    const float* mb2 = (const float*)d_in[7];
    const float* pW1 = (const float*)d_in[8];
    const float* pb1 = (const float*)d_in[9];
    const float* pW2 = (const float*)d_in[10];
    const float* pb2 = (const float*)d_in[11];
    const float* pW3 = (const float*)d_in[12];
    const float* pb3 = (const float*)d_in[13];

    int B = in_sizes[1] / 2;       // x is (B, 2)
    int npairs = B / 2;
    int threads = NTHR;
    long long tot_threads = (npairs + NPAIR - 1) / NPAIR;
    int blocks = (int)((tot_threads + threads - 1) / threads);

    odefunc_kernel<<<blocks, threads>>>(x, mW0, mb0, mW1, mb1, mW2, mb2,
                                        pW1, pb1, pW2, pb2, pW3, pb3,
                                        (float*)d_out, npairs);
}